// round 16
// baseline (speedup 1.0000x reference)
#include <cuda_runtime.h>
#include <cstdint>

// Problem constants (fixed by the reference): B=4, N=4096, D=256, K=2048
#define PB 4
#define PN 4096
#define PD 256
#define PK 2048

// Scratch (device globals — no allocation allowed)
__device__ unsigned long long g_keys[PB * PN];
__device__ float              g_scores[PB * PN];
__device__ int                g_selidx[PB * PK];
__device__ float              g_selval[PB * PK];

// ---------------------------------------------------------------------------
// Kernel 1: XLA:CPU (aarch64) replica — strength-reduced mul+reduce fusion,
// LLVM loop-vectorized with VF=4 (NEON), IC=2, fast-math FMA contraction:
//   acc0[l] = sum_{i=0..31} fma(h[8i+l],   s[8i+l],   acc0[l])
//   acc1[l] = sum_{i=0..31} fma(h[8i+4+l], s[8i+4+l], acc1[l])
//   w[l]    = acc0[l] + acc1[l]                (lane-wise vector add)
//   total   = (w0+w1) + (w2+w3)                (NEON faddp reduce)
//   logistic = 1/(1+expf(-x)) — formulation locked; exp bits immaterial.
// One thread per row (exact serial chain), 256 rows per block.
// ---------------------------------------------------------------------------
__global__ void __launch_bounds__(256) score_kernel(
    const float* __restrict__ h, const float* __restrict__ sf)
{
    int row = blockIdx.x * 256 + threadIdx.x;          // [0, B*N)
    int b   = row >> 12;                               // / PN

    const float4* hr = reinterpret_cast<const float4*>(h)  + (size_t)row * (PD / 4);
    const float4* s4 = reinterpret_cast<const float4*>(sf) + (size_t)b   * (PD / 4);

    // acc0 lanes
    float a00 = 0.f, a01 = 0.f, a02 = 0.f, a03 = 0.f;
    // acc1 lanes
    float a10 = 0.f, a11 = 0.f, a12 = 0.f, a13 = 0.f;

    #pragma unroll 8
    for (int i = 0; i < 32; i++) {
        float4 p0 = __ldg(hr + 2 * i);        // elements 8i .. 8i+3
        float4 q0 = __ldg(s4 + 2 * i);
        float4 p1 = __ldg(hr + 2 * i + 1);    // elements 8i+4 .. 8i+7
        float4 q1 = __ldg(s4 + 2 * i + 1);
        a00 = __fmaf_rn(p0.x, q0.x, a00);
        a01 = __fmaf_rn(p0.y, q0.y, a01);
        a02 = __fmaf_rn(p0.z, q0.z, a02);
        a03 = __fmaf_rn(p0.w, q0.w, a03);
        a10 = __fmaf_rn(p1.x, q1.x, a10);
        a11 = __fmaf_rn(p1.y, q1.y, a11);
        a12 = __fmaf_rn(p1.z, q1.z, a12);
        a13 = __fmaf_rn(p1.w, q1.w, a13);
    }

    // lane-wise vector add of the two accumulators
    float w0 = __fadd_rn(a00, a10);
    float w1 = __fadd_rn(a01, a11);
    float w2 = __fadd_rn(a02, a12);
    float w3 = __fadd_rn(a03, a13);
    // NEON faddp reduction: (w0+w1) + (w2+w3)
    float acc = __fadd_rn(__fadd_rn(w0, w1), __fadd_rn(w2, w3));

    float sc = 1.0f / (1.0f + expf(-acc));   // logistic, IEEE div
    g_scores[row] = sc;
    unsigned u = __float_as_uint(sc);
    // monotonic float->uint mapping
    u ^= (unsigned)((int)u >> 31) | 0x80000000u;
    unsigned n = (unsigned)(row & (PN - 1));
    // low word: smaller index -> larger key -> wins ties
    // (stable sort of lax.top_k: ascending index within equal scores)
    g_keys[row] = ((unsigned long long)u << 32) | (0xFFFFFFFFu - n);
}

// ---------------------------------------------------------------------------
// Kernel 2: rank each element against all N keys of its batch; keys are
// strictly unique so ranks form a permutation. rank < K => scatter to its
// sorted output slot.
// Grid: (N/128, B), 512 threads. Thread (e,c): element e of this block's 128,
// chunk c of 4 interleaved key chunks. smem keys broadcast, conflict-free.
// ---------------------------------------------------------------------------
__global__ void __launch_bounds__(512) rank_kernel()
{
    __shared__ unsigned long long sk[PN];
    int b = blockIdx.y;
    const unsigned long long* kb = g_keys + (size_t)b * PN;

    for (int i = threadIdx.x; i < PN; i += 512)
        sk[i] = kb[i];
    __syncthreads();

    int c = threadIdx.x & 3;       // chunk 0..3
    int e = threadIdx.x >> 2;      // element 0..127
    int n = blockIdx.x * 128 + e;
    unsigned long long mk = sk[n];

    int cnt = 0;
    #pragma unroll 8
    for (int i = 0; i < PN / 4; i++) {
        cnt += (sk[4 * i + c] > mk) ? 1 : 0;
    }
    // reduce over the 4 chunk-threads (consecutive lanes)
    cnt += __shfl_down_sync(0xffffffffu, cnt, 1);
    cnt += __shfl_down_sync(0xffffffffu, cnt, 2);

    if (c == 0 && cnt < PK) {
        g_selidx[b * PK + cnt] = n;
        g_selval[b * PK + cnt] = g_scores[(size_t)b * PN + n];
    }
}

// ---------------------------------------------------------------------------
// Kernel 3: gather. One block per output row (B*K = 8192 blocks, 256 threads).
//   new_g[b,k,:] = g1[b, idx, :]            (4096 floats = 1024 float4)
//   new_h[b,k,:] = h[b, idx, :] * val       (256 floats = 64 float4)
// out layout: [ new_g (B*K*N) | new_h (B*K*D) ]
// ---------------------------------------------------------------------------
__global__ void __launch_bounds__(256) gather_kernel(
    const float* __restrict__ g1, const float* __restrict__ h,
    float* __restrict__ out)
{
    int blk = blockIdx.x;          // [0, B*K)
    int b   = blk >> 11;           // / PK
    int idx = g_selidx[blk];
    float val = g_selval[blk];

    const float4* gsrc = reinterpret_cast<const float4*>(g1)
                       + ((size_t)b * PN + idx) * (PN / 4);
    float4* gdst = reinterpret_cast<float4*>(out) + (size_t)blk * (PN / 4);

    int t = threadIdx.x;
    #pragma unroll
    for (int i = 0; i < 4; i++)
        gdst[t + 256 * i] = gsrc[t + 256 * i];

    if (t < PD / 4) {
        const float4* hsrc = reinterpret_cast<const float4*>(h)
                           + ((size_t)b * PN + idx) * (PD / 4);
        float4* hdst = reinterpret_cast<float4*>(out)
                     + (size_t)(PB * PK) * (PN / 4)      // past new_g
                     + (size_t)blk * (PD / 4);
        float4 v = hsrc[t];
        v.x *= val; v.y *= val; v.z *= val; v.w *= val;
        hdst[t] = v;
    }
}

// ---------------------------------------------------------------------------
extern "C" void kernel_launch(void* const* d_in, const int* in_sizes, int n_in,
                              void* d_out, int out_size)
{
    const float* g1 = (const float*)d_in[0];   // [B, N, N]
    const float* h  = (const float*)d_in[1];   // [B, N, D]
    const float* sf = (const float*)d_in[2];   // [B, 1, D]
    float* out = (float*)d_out;

    // 1) scores + keys (XLA:CPU + LLVM autovec VF4/IC2 replica)
    score_kernel<<<(PB * PN) / 256, 256>>>(h, sf);

    // 2) ranks -> sorted selection
    dim3 rgrid(PN / 128, PB);
    rank_kernel<<<rgrid, 512>>>();

    // 3) gather rows
    gather_kernel<<<PB * PK, 256>>>(g1, h, out);
}

// round 17
// speedup vs baseline: 1.0408x; 1.0408x over previous
#include <cuda_runtime.h>
#include <cstdint>

// Problem constants (fixed by the reference): B=4, N=4096, D=256, K=2048
#define PB 4
#define PN 4096
#define PD 256
#define PK 2048

// Scratch (device globals — no allocation allowed)
__device__ unsigned long long g_keys[PB * PN];
__device__ float              g_scores[PB * PN];
__device__ int                g_selidx[PB * PK];
__device__ float              g_selval[PB * PK];

// ---------------------------------------------------------------------------
// Kernel 1: XLA:CPU (aarch64) replica — LLVM loop-vectorized VF=4, IC=2,
// FMA-contracted — BIT-EXACT chain, now split 2 threads/row for latency:
//   thread half=0: acc0[l] = sum_i fma(h[8i+l],   s[8i+l],   .)  (float4 @2i)
//   thread half=1: acc1[l] = sum_i fma(h[8i+4+l], s[8i+4+l], .)  (float4 @2i+1)
//   pair fold (half 0, original operand order):
//     w[l] = acc0[l] + acc1[l];  total = (w0+w1) + (w2+w3)
//   logistic = 1/(1+expf(-x)).
// 128 threads/block => 64 rows/block, 256 blocks (all SMs engaged).
// ---------------------------------------------------------------------------
__global__ void __launch_bounds__(128) score_kernel(
    const float* __restrict__ h, const float* __restrict__ sf)
{
    int gtid = blockIdx.x * 128 + threadIdx.x;
    int row  = gtid >> 1;          // [0, B*N)
    int half = gtid & 1;           // 0 -> acc0 chains, 1 -> acc1 chains
    int b    = row >> 12;          // / PN

    const float4* hr = reinterpret_cast<const float4*>(h)  + (size_t)row * (PD / 4);
    const float4* s4 = reinterpret_cast<const float4*>(sf) + (size_t)b   * (PD / 4);

    float ax = 0.f, ay = 0.f, az = 0.f, aw = 0.f;
    #pragma unroll 8
    for (int i = 0; i < 32; i++) {
        float4 p = __ldg(hr + 2 * i + half);
        float4 q = __ldg(s4 + 2 * i + half);
        ax = __fmaf_rn(p.x, q.x, ax);
        ay = __fmaf_rn(p.y, q.y, ay);
        az = __fmaf_rn(p.z, q.z, az);
        aw = __fmaf_rn(p.w, q.w, aw);
    }

    // exchange with pair partner (lane ^ 1)
    float bx = __shfl_xor_sync(0xffffffffu, ax, 1);
    float by = __shfl_xor_sync(0xffffffffu, ay, 1);
    float bz = __shfl_xor_sync(0xffffffffu, az, 1);
    float bw = __shfl_xor_sync(0xffffffffu, aw, 1);

    if (half == 0) {
        // lane-wise vector add: acc0 + acc1 (operand order preserved)
        float w0 = __fadd_rn(ax, bx);
        float w1 = __fadd_rn(ay, by);
        float w2 = __fadd_rn(az, bz);
        float w3 = __fadd_rn(aw, bw);
        // NEON faddp reduction: (w0+w1) + (w2+w3)
        float acc = __fadd_rn(__fadd_rn(w0, w1), __fadd_rn(w2, w3));

        float sc = 1.0f / (1.0f + expf(-acc));   // logistic, IEEE div
        g_scores[row] = sc;
        unsigned u = __float_as_uint(sc);
        u ^= (unsigned)((int)u >> 31) | 0x80000000u;   // monotonic map
        unsigned n = (unsigned)(row & (PN - 1));
        // low word: smaller index -> larger key -> wins ties (stable top_k)
        g_keys[row] = ((unsigned long long)u << 32) | (0xFFFFFFFFu - n);
    }
}

// ---------------------------------------------------------------------------
// Kernel 2: rank-select. Keys strictly unique => rank is a permutation;
// rank < K scatters to the sorted output slot.
// Grid: (N/128, B), 512 threads. Thread (e,c): element e, chunk c of 4.
// Inner loop vectorized: ulonglong2 smem loads (lanes c=0..3 cover 64B
// contiguous, broadcast across the 8 e-groups -> conflict-free).
// ---------------------------------------------------------------------------
__global__ void __launch_bounds__(512) rank_kernel()
{
    __shared__ __align__(16) unsigned long long sk[PN];
    int b = blockIdx.y;
    const unsigned long long* kb = g_keys + (size_t)b * PN;

    for (int i = threadIdx.x; i < PN; i += 512)
        sk[i] = kb[i];
    __syncthreads();

    int c = threadIdx.x & 3;       // chunk 0..3
    int e = threadIdx.x >> 2;      // element 0..127
    int n = blockIdx.x * 128 + e;
    unsigned long long mk = sk[n];

    const ulonglong2* sk2 = reinterpret_cast<const ulonglong2*>(sk);  // 2048
    int cnt = 0;
    #pragma unroll 8
    for (int i = 0; i < PN / 8; i++) {       // 512 iters, 2 keys each
        ulonglong2 k = sk2[4 * i + c];
        cnt += (k.x > mk) ? 1 : 0;
        cnt += (k.y > mk) ? 1 : 0;
    }
    // reduce over the 4 chunk-threads (consecutive lanes)
    cnt += __shfl_down_sync(0xffffffffu, cnt, 1);
    cnt += __shfl_down_sync(0xffffffffu, cnt, 2);

    if (c == 0 && cnt < PK) {
        g_selidx[b * PK + cnt] = n;
        g_selval[b * PK + cnt] = g_scores[(size_t)b * PN + n];
    }
}

// ---------------------------------------------------------------------------
// Kernel 3: gather. One block per output row (B*K = 8192 blocks, 256 threads).
//   new_g[b,k,:] = g1[b, idx, :]            (4096 floats = 1024 float4)
//   new_h[b,k,:] = h[b, idx, :] * val       (256 floats = 64 float4)
// out layout: [ new_g (B*K*N) | new_h (B*K*D) ]   — BW-floor bound.
// ---------------------------------------------------------------------------
__global__ void __launch_bounds__(256) gather_kernel(
    const float* __restrict__ g1, const float* __restrict__ h,
    float* __restrict__ out)
{
    int blk = blockIdx.x;          // [0, B*K)
    int b   = blk >> 11;           // / PK
    int idx = g_selidx[blk];
    float val = g_selval[blk];

    const float4* gsrc = reinterpret_cast<const float4*>(g1)
                       + ((size_t)b * PN + idx) * (PN / 4);
    float4* gdst = reinterpret_cast<float4*>(out) + (size_t)blk * (PN / 4);

    int t = threadIdx.x;
    #pragma unroll
    for (int i = 0; i < 4; i++)
        gdst[t + 256 * i] = __ldg(gsrc + t + 256 * i);

    if (t < PD / 4) {
        const float4* hsrc = reinterpret_cast<const float4*>(h)
                           + ((size_t)b * PN + idx) * (PD / 4);
        float4* hdst = reinterpret_cast<float4*>(out)
                     + (size_t)(PB * PK) * (PN / 4)      // past new_g
                     + (size_t)blk * (PD / 4);
        float4 v = __ldg(hsrc + t);
        v.x *= val; v.y *= val; v.z *= val; v.w *= val;
        hdst[t] = v;
    }
}

// ---------------------------------------------------------------------------
extern "C" void kernel_launch(void* const* d_in, const int* in_sizes, int n_in,
                              void* d_out, int out_size)
{
    const float* g1 = (const float*)d_in[0];   // [B, N, N]
    const float* h  = (const float*)d_in[1];   // [B, N, D]
    const float* sf = (const float*)d_in[2];   // [B, 1, D]
    float* out = (float*)d_out;

    // 1) scores + keys (bit-exact chain, 2 threads/row, 256 blocks)
    score_kernel<<<(PB * PN * 2) / 128, 128>>>(h, sf);

    // 2) ranks -> sorted selection (vectorized smem compares)
    dim3 rgrid(PN / 128, PB);
    rank_kernel<<<rgrid, 512>>>();

    // 3) gather rows (BW-floor bound)
    gather_kernel<<<PB * PK, 256>>>(g1, h, out);
}